// round 3
// baseline (speedup 1.0000x reference)
#include <cuda_runtime.h>

typedef unsigned long long ull;

#define cB 32
#define cT 1024
#define cIN 1024
#define cNH 8
#define cD 128
#define cG 4
#define cH 1024
#define cQ 512   // D*G

// Scratch (static __device__ arrays: allocation-free per harness rules)
__device__ float g_Wx[(size_t)cT * cB * cNH * cQ];   // 512 MB: gate preactivations, layout (T,B,NH,G,D)
__device__ float g_hs0[(size_t)cT * cB * cNH * cD];  // 128 MB: layer-0 hidden states, layout (T,B,NH,D)

// ---------------------------------------------------------------------------
// Packed fp32x2 FMA (Blackwell): two fp32 FMAs per instruction.
// ---------------------------------------------------------------------------
__device__ __forceinline__ ull ffma2(ull a, ull b, ull c) {
    ull d;
    asm("fma.rn.f32x2 %0, %1, %2, %3;" : "=l"(d) : "l"(a), "l"(b), "l"(c));
    return d;
}
__device__ __forceinline__ float2 u2f2(ull u) {
    float2 f;
    asm("mov.b64 {%0, %1}, %2;" : "=f"(f.x), "=f"(f.y) : "l"(u));
    return f;
}
__device__ __forceinline__ float sigf(float x) { return 1.0f / (1.0f + __expf(-x)); }
__device__ __forceinline__ float tanhf_(float x) { return 1.0f - 2.0f / (__expf(2.0f * x) + 1.0f); }

// ---------------------------------------------------------------------------
// Tiled fp32 GEMM with K-pair f32x2 accumulation.
//   C[r][e] = sum_k A[r][k] * Bm[e][k] + bias[e]   (both operands K-major)
// MODE 0: input projection  -> writes g_Wx layout (T,B,NH,G,D)
// MODE 1: inter-layer proj  -> writes g_Wx layout (T,B,NH, (e&3)*128 + (e>>2))
// Tile 128x128, 256 threads, 8x8 per thread, double-buffered SMEM.
// ---------------------------------------------------------------------------
template <int KK, int MODE>
__global__ __launch_bounds__(256) void gemm_kernel(
    const float* __restrict__ A, const float* __restrict__ Bm,
    const float* __restrict__ bias, float* __restrict__ out)
{
    __shared__ float As[2][128][20];  // [m][k], rows padded to 20 floats (80B, 16B-aligned)
    __shared__ float Bs[2][128][20];  // [n][k]
    const int tid = threadIdx.x;
    const int tx = tid & 15, ty = tid >> 4;
    const int mBase = blockIdx.y * 128;
    const int nBase = blockIdx.x * 128;
    constexpr int NCH = KK / 16;

    float4 aR[2], bR[2];
    ull acc[8][8];
#pragma unroll
    for (int i = 0; i < 8; i++)
#pragma unroll
        for (int j = 0; j < 8; j++) acc[i][j] = 0ull;

    // preload chunk 0
#pragma unroll
    for (int s = 0; s < 2; s++) {
        int lin = s * 256 + tid;
        int row = lin >> 2, kv = lin & 3;
        aR[s] = *(const float4*)(A + (size_t)(mBase + row) * KK + kv * 4);
        bR[s] = *(const float4*)(Bm + (size_t)(nBase + row) * KK + kv * 4);
    }
#pragma unroll
    for (int s = 0; s < 2; s++) {
        int lin = s * 256 + tid;
        int row = lin >> 2, kv = lin & 3;
        *(float4*)&As[0][row][kv * 4] = aR[s];
        *(float4*)&Bs[0][row][kv * 4] = bR[s];
    }
    __syncthreads();

    for (int c = 0; c < NCH; c++) {
        const int buf = c & 1;
        if (c + 1 < NCH) {  // prefetch next chunk to registers
            const int k0 = (c + 1) * 16;
#pragma unroll
            for (int s = 0; s < 2; s++) {
                int lin = s * 256 + tid;
                int row = lin >> 2, kv = lin & 3;
                aR[s] = *(const float4*)(A + (size_t)(mBase + row) * KK + k0 + kv * 4);
                bR[s] = *(const float4*)(Bm + (size_t)(nBase + row) * KK + k0 + kv * 4);
            }
        }
#pragma unroll
        for (int k4 = 0; k4 < 4; k4++) {
            longlong2 bv[8];
#pragma unroll
            for (int j = 0; j < 8; j++)
                bv[j] = *(const longlong2*)&Bs[buf][tx + 16 * j][k4 * 4];
#pragma unroll
            for (int i = 0; i < 8; i++) {
                longlong2 av = *(const longlong2*)&As[buf][ty + 16 * i][k4 * 4];
#pragma unroll
                for (int j = 0; j < 8; j++) {
                    acc[i][j] = ffma2((ull)av.x, (ull)bv[j].x, acc[i][j]);
                    acc[i][j] = ffma2((ull)av.y, (ull)bv[j].y, acc[i][j]);
                }
            }
        }
        if (c + 1 < NCH) {
            const int nb = 1 - buf;
#pragma unroll
            for (int s = 0; s < 2; s++) {
                int lin = s * 256 + tid;
                int row = lin >> 2, kv = lin & 3;
                *(float4*)&As[nb][row][kv * 4] = aR[s];
                *(float4*)&Bs[nb][row][kv * 4] = bR[s];
            }
        }
        __syncthreads();
    }

    // epilogue: reduce lanes, add bias, permuted store
    float bs[8];
#pragma unroll
    for (int j = 0; j < 8; j++) bs[j] = bias[nBase + tx + 16 * j];
#pragma unroll
    for (int i = 0; i < 8; i++) {
        const int r = mBase + ty + 16 * i;
#pragma unroll
        for (int j = 0; j < 8; j++) {
            const int e = nBase + tx + 16 * j;
            float2 v = u2f2(acc[i][j]);
            float val = v.x + v.y + bs[j];
            if (MODE == 0) {
                // A rows are (b,t); W row e = g*1024 + n*128 + d
                int b = r >> 10, t = r & 1023;
                int g = e >> 10, nh = (e >> 7) & 7, d = e & 127;
                out[(((size_t)t * cB + b) * cNH + nh) * cQ + (size_t)g * cD + d] = val;
            } else {
                // A rows are (t,b,n); W2 row e maps to (d = e>>2, g = e&3)
                out[(size_t)r * cQ + (size_t)(e & 3) * cD + (e >> 2)] = val;
            }
        }
    }
}

// ---------------------------------------------------------------------------
// Persistent per-(head, batch-pair) LSTM scan.
// Grid: 128 CTAs (8 heads x 16 batch-pairs), 256 threads.
// Thread t owns gate rows q0=t (R row in registers) and q1=t+256 (R row in SMEM).
// h-state: SMEM, double-buffered. c-state: registers (thread t owns (b,d)=(t>>7, t&127)).
// Gate rows indexed q = g*128 + d (matches g_Wx layout).
// ---------------------------------------------------------------------------
__global__ __launch_bounds__(256) void lstm_scan_kernel(
    const float* __restrict__ Wx, const float* __restrict__ R,
    const float* __restrict__ Bg, float* __restrict__ hs_out,
    float* __restrict__ out, int layer)
{
    extern __shared__ char smem[];
    longlong2* R1s = (longlong2*)smem;              // [32 j4][256 q] = 128 KB
    ull* hbuf = (ull*)(smem + 131072);              // [2 buf][2 b][64 jpair] = 2 KB
    float* pre = (float*)(smem + 131072 + 2048);    // [2 b][512 q] = 4 KB

    const int tid = threadIdx.x;
    const int n = blockIdx.x >> 4;
    const int b0 = (blockIdx.x & 15) * 2;

    const float* Rh = R + (size_t)(layer * cNH + n) * cD * cG * cD;

    // R row q0 -> registers (64 packed k-pairs = 128 regs)
    const int q0 = tid, d0 = q0 & 127, g0 = q0 >> 7;
    const ull* r0g = (const ull*)(Rh + ((size_t)d0 * 4 + g0) * cD);
    ull R0[64];
#pragma unroll
    for (int p = 0; p < 64; p++) R0[p] = r0g[p];

    // R row q1 -> SMEM
    const int q1 = 256 + tid, d1 = q1 & 127, g1 = q1 >> 7;
    const longlong2* r1g = (const longlong2*)(Rh + ((size_t)d1 * 4 + g1) * cD);
#pragma unroll
    for (int j4 = 0; j4 < 32; j4++) R1s[j4 * 256 + tid] = r1g[j4];

    const float bg0 = Bg[((size_t)(layer * cNH + n) * cD + d0) * 4 + g0];
    const float bg1 = Bg[((size_t)(layer * cNH + n) * cD + d1) * 4 + g1];

    hbuf[tid] = 0ull;  // zero both h buffers (h(t=0) = 0)
    float c = 0.0f;
    const int ub = tid >> 7, ud = tid & 127;  // update-phase ownership: (batch-sel, d)

    const float* wxBase = Wx + ((size_t)b0 * cNH + n) * cQ;
    const size_t wxStep = (size_t)cB * cNH * cQ;   // per-t stride
    const size_t HN_OFF = (size_t)cB * cT * cH;

    __syncthreads();

    for (int t = 0; t < cT; t++) {
        // prefetch this step's Wx contributions (consumed after the j-loop)
        const float* wxp = wxBase + (size_t)t * wxStep;
        const float wx00 = wxp[q0];
        const float wx01 = wxp[cNH * cQ + q0];
        const float wx10 = wxp[q1];
        const float wx11 = wxp[cNH * cQ + q1];

        const int cur = t & 1;
        const longlong2* hA = (const longlong2*)(hbuf + (size_t)cur * 128);       // batch b0
        const longlong2* hB = (const longlong2*)(hbuf + (size_t)cur * 128 + 64);  // batch b0+1

        ull a00 = 0ull, a01 = 0ull, a10 = 0ull, a11 = 0ull;
#pragma unroll
        for (int j4 = 0; j4 < 32; j4++) {
            const longlong2 ha = hA[j4];
            const longlong2 hb = hB[j4];
            const longlong2 r1 = R1s[j4 * 256 + tid];
            a00 = ffma2(R0[2 * j4], (ull)ha.x, a00);
            a00 = ffma2(R0[2 * j4 + 1], (ull)ha.y, a00);
            a01 = ffma2(R0[2 * j4], (ull)hb.x, a01);
            a01 = ffma2(R0[2 * j4 + 1], (ull)hb.y, a01);
            a10 = ffma2((ull)r1.x, (ull)ha.x, a10);
            a10 = ffma2((ull)r1.y, (ull)ha.y, a10);
            a11 = ffma2((ull)r1.x, (ull)hb.x, a11);
            a11 = ffma2((ull)r1.y, (ull)hb.y, a11);
        }
        float2 v;
        v = u2f2(a00); pre[q0]       = v.x + v.y + wx00 + bg0;
        v = u2f2(a01); pre[512 + q0] = v.x + v.y + wx01 + bg0;
        v = u2f2(a10); pre[q1]       = v.x + v.y + wx10 + bg1;
        v = u2f2(a11); pre[512 + q1] = v.x + v.y + wx11 + bg1;
        __syncthreads();

        // gate fusion + state update (thread owns (ub, ud))
        const float pi = pre[ub * 512 + 0 * cD + ud];
        const float pf = pre[ub * 512 + 1 * cD + ud];
        const float pz = pre[ub * 512 + 2 * cD + ud];
        const float po = pre[ub * 512 + 3 * cD + ud];
        const float gi = sigf(pi), gf = sigf(pf), gz = tanhf_(pz), go = sigf(po);
        c = gf * c + gi * gz;
        const float hn = go * tanhf_(c);

        const int nxt = (t + 1) & 1;
        float* hw = (float*)(hbuf + (size_t)nxt * 128 + (size_t)ub * 64);
        hw[ud] = hn;  // packed j-pair layout == contiguous h vector

        const int bg_ = b0 + ub;
        if (layer == 0)
            hs_out[(((size_t)t * cB + bg_) * cNH + n) * cD + ud] = hn;
        else
            out[((size_t)bg_ * cT + t) * cH + (size_t)n * cD + ud] = hn;

        if (t == cT - 1) {
            out[HN_OFF + (size_t)layer * cB * cH + (size_t)bg_ * cH + (size_t)n * cD + ud] = hn;
            out[HN_OFF + (size_t)2 * cB * cH + (size_t)layer * cB * cH + (size_t)bg_ * cH + (size_t)n * cD + ud] = c;
        }
        __syncthreads();  // h(t+1) visible before next step's matmul
    }
}

// ---------------------------------------------------------------------------
extern "C" void kernel_launch(void* const* d_in, const int* in_sizes, int n_in,
                              void* d_out, int out_size) {
    const float* x   = (const float*)d_in[0];  // (B,T,IN)
    const float* W   = (const float*)d_in[1];  // (4H, IN)
    const float* Wb  = (const float*)d_in[2];  // (4H)
    const float* W2  = (const float*)d_in[3];  // (4D, D)
    const float* W2b = (const float*)d_in[4];  // (4D)
    const float* R   = (const float*)d_in[5];  // (L,NH,D,G,D)
    const float* Bg  = (const float*)d_in[6];  // (L,NH,D,G)
    float* out = (float*)d_out;

    float* Wx;  cudaGetSymbolAddress((void**)&Wx, g_Wx);
    float* hs0; cudaGetSymbolAddress((void**)&hs0, g_hs0);

    const int SMEM_SCAN = 131072 + 2048 + 4096;
    cudaFuncSetAttribute(lstm_scan_kernel,
                         cudaFuncAttributeMaxDynamicSharedMemorySize, SMEM_SCAN);

    // Phase 1: input projection (32768 x 4096 x 1024)
    gemm_kernel<cIN, 0><<<dim3(32, 256), 256>>>(x, W, Wb, Wx);
    // Phase 2: layer-0 scan
    lstm_scan_kernel<<<128, 256, SMEM_SCAN>>>(Wx, R, Bg, hs0, out, 0);
    // Phase 3: inter-layer projection (262144 x 512 x 128)
    gemm_kernel<cD, 1><<<dim3(4, 2048), 256>>>(hs0, W2, W2b, Wx);
    // Phase 4: layer-1 scan (writes h, hn, cn)
    lstm_scan_kernel<<<128, 256, SMEM_SCAN>>>(Wx, R, Bg, hs0, out, 1);
}

// round 4
// speedup vs baseline: 1.6500x; 1.6500x over previous
#include <cuda_runtime.h>
#include <cuda_bf16.h>

typedef unsigned long long ull;
typedef unsigned int uint32;

#define cB 32
#define cT 1024
#define cIN 1024
#define cNH 8
#define cD 128
#define cG 4
#define cH 1024
#define cQ 512   // D*G

// Scratch (static __device__ arrays: allocation-free per harness rules)
__device__ float g_Wx[(size_t)cT * cB * cNH * cQ];   // gate preactivations, layout (T,B,NH,G,D)
__device__ float g_hs0[(size_t)cT * cB * cNH * cD];  // layer-0 hidden states, layout (T,B,NH,D)
__device__ __nv_bfloat16 g_xhi[(size_t)cB * cT * cIN];
__device__ __nv_bfloat16 g_xlo[(size_t)cB * cT * cIN];
__device__ __nv_bfloat16 g_Whi[(size_t)cG * cH * cIN];
__device__ __nv_bfloat16 g_Wlo[(size_t)cG * cH * cIN];

// ---------------------------------------------------------------------------
// Packed fp32x2 FMA (Blackwell)
// ---------------------------------------------------------------------------
__device__ __forceinline__ ull ffma2(ull a, ull b, ull c) {
    ull d;
    asm("fma.rn.f32x2 %0, %1, %2, %3;" : "=l"(d) : "l"(a), "l"(b), "l"(c));
    return d;
}
__device__ __forceinline__ float2 u2f2(ull u) {
    float2 f;
    asm("mov.b64 {%0, %1}, %2;" : "=f"(f.x), "=f"(f.y) : "l"(u));
    return f;
}
__device__ __forceinline__ float sigf(float x) { return 1.0f / (1.0f + __expf(-x)); }
__device__ __forceinline__ float tanhf_(float x) { return 1.0f - 2.0f / (__expf(2.0f * x) + 1.0f); }

// ---------------------------------------------------------------------------
// fp32 -> bf16 hi/lo split (bf16x3 scheme)
// ---------------------------------------------------------------------------
__global__ __launch_bounds__(256) void split_kernel(
    const float* __restrict__ in, __nv_bfloat16* __restrict__ hi,
    __nv_bfloat16* __restrict__ lo)
{
    size_t i = ((size_t)blockIdx.x * 256 + threadIdx.x) * 4;
    float4 v = *(const float4*)(in + i);
    __nv_bfloat16 h[4], l[4];
    float vv[4] = {v.x, v.y, v.z, v.w};
#pragma unroll
    for (int k = 0; k < 4; k++) {
        h[k] = __float2bfloat16_rn(vv[k]);
        l[k] = __float2bfloat16_rn(vv[k] - __bfloat162float(h[k]));
    }
    *(uint2*)(hi + i) = *(uint2*)h;
    *(uint2*)(lo + i) = *(uint2*)l;
}

// ---------------------------------------------------------------------------
// mma.sync helpers
// ---------------------------------------------------------------------------
__device__ __forceinline__ void ldsm4(uint32* r, const __nv_bfloat16* p) {
    uint32 a = (uint32)__cvta_generic_to_shared(p);
    asm volatile("ldmatrix.sync.aligned.m8n8.x4.shared.b16 {%0,%1,%2,%3}, [%4];"
                 : "=r"(r[0]), "=r"(r[1]), "=r"(r[2]), "=r"(r[3]) : "r"(a));
}
__device__ __forceinline__ void mma16816(float* c, const uint32* a, const uint32* b) {
    asm volatile(
        "mma.sync.aligned.m16n8k16.row.col.f32.bf16.bf16.f32 "
        "{%0,%1,%2,%3}, {%4,%5,%6,%7}, {%8,%9}, {%0,%1,%2,%3};"
        : "+f"(c[0]), "+f"(c[1]), "+f"(c[2]), "+f"(c[3])
        : "r"(a[0]), "r"(a[1]), "r"(a[2]), "r"(a[3]), "r"(b[0]), "r"(b[1]));
}

// ---------------------------------------------------------------------------
// Phase-1 GEMM on tensor cores, bf16x3: C = Ahi*Bhi + Ahi*Blo + Alo*Bhi + bias
// A (32768 x 1024) row-major, B (4096 x 1024) row-major (K-major both).
// CTA tile 128x128, 8 warps (2x4), warp tile 64x32, BK=32, double-buffered.
// Epilogue scatters to g_Wx layout (T,B,NH,G,D).
// ---------------------------------------------------------------------------
__global__ __launch_bounds__(256) void gemm_mma0(
    const __nv_bfloat16* __restrict__ Ahi, const __nv_bfloat16* __restrict__ Alo,
    const __nv_bfloat16* __restrict__ Bhi, const __nv_bfloat16* __restrict__ Blo,
    const float* __restrict__ bias, float* __restrict__ out)
{
    extern __shared__ __nv_bfloat16 sm[];
    constexpr int LDSW = 40;          // padded row stride (bf16) -> conflict-free ldmatrix
    constexpr int BUF = 128 * LDSW;   // one buffer of one array

    const int tid = threadIdx.x;
    const int lane = tid & 31, w = tid >> 5;
    const int wm = w & 1, wn = w >> 1;
    const int mBase = blockIdx.y * 128;
    const int nBase = blockIdx.x * 128;

    float acc[4][4][4];
#pragma unroll
    for (int i = 0; i < 4; i++)
#pragma unroll
        for (int j = 0; j < 4; j++)
#pragma unroll
            for (int r = 0; r < 4; r++) acc[i][j][r] = 0.0f;

    uint4 pr[8];
    const int lrow0 = (0 * 256 + tid) >> 2, lkv0 = (0 * 256 + tid) & 3;
    const int lrow1 = (1 * 256 + tid) >> 2, lkv1 = (1 * 256 + tid) & 3;

#define GLOAD(cc)                                                              \
    {                                                                          \
        int k0 = (cc) * 32;                                                    \
        size_t a0 = (size_t)(mBase + lrow0) * cIN + k0 + lkv0 * 8;             \
        size_t a1 = (size_t)(mBase + lrow1) * cIN + k0 + lkv1 * 8;             \
        size_t b0 = (size_t)(nBase + lrow0) * cIN + k0 + lkv0 * 8;             \
        size_t b1 = (size_t)(nBase + lrow1) * cIN + k0 + lkv1 * 8;             \
        pr[0] = *(const uint4*)(Ahi + a0); pr[1] = *(const uint4*)(Ahi + a1);  \
        pr[2] = *(const uint4*)(Alo + a0); pr[3] = *(const uint4*)(Alo + a1);  \
        pr[4] = *(const uint4*)(Bhi + b0); pr[5] = *(const uint4*)(Bhi + b1);  \
        pr[6] = *(const uint4*)(Blo + b0); pr[7] = *(const uint4*)(Blo + b1);  \
    }
#define SSTORE(bf)                                                             \
    {                                                                          \
        int o0 = (bf) * BUF + lrow0 * LDSW + lkv0 * 8;                         \
        int o1 = (bf) * BUF + lrow1 * LDSW + lkv1 * 8;                         \
        *(uint4*)(sm + o0) = pr[0];            *(uint4*)(sm + o1) = pr[1];     \
        *(uint4*)(sm + 2 * BUF + o0) = pr[2];  *(uint4*)(sm + 2 * BUF + o1) = pr[3]; \
        *(uint4*)(sm + 4 * BUF + o0) = pr[4];  *(uint4*)(sm + 4 * BUF + o1) = pr[5]; \
        *(uint4*)(sm + 6 * BUF + o0) = pr[6];  *(uint4*)(sm + 6 * BUF + o1) = pr[7]; \
    }

    GLOAD(0);
    SSTORE(0);
    __syncthreads();

    for (int c = 0; c < 32; c++) {
        const int buf = c & 1;
        if (c + 1 < 32) GLOAD(c + 1);
#pragma unroll
        for (int st = 0; st < 2; st++) {
            const int kb = st * 16;
            uint32 ahi[4][4], alo[4][4], bhi[4][2], blo[4][2];
            // A fragments: addr row = m0 + lane%16, col = kb + (lane/16)*8
            const int arow = (lane & 15);
            const int acol = kb + (lane >> 4) * 8;
#pragma unroll
            for (int i = 0; i < 4; i++) {
                int off = buf * BUF + (wm * 64 + i * 16 + arow) * LDSW + acol;
                ldsm4(ahi[i], sm + off);
                ldsm4(alo[i], sm + 2 * BUF + off);
            }
            // B fragments: row = n0 + (lane&7) + ((lane>>4)<<3), col = kb + ((lane>>3)&1)*8
            const int brow = (lane & 7) + ((lane >> 4) << 3);
            const int bcol = kb + ((lane >> 3) & 1) * 8;
#pragma unroll
            for (int p = 0; p < 2; p++) {
                int off = buf * BUF + (wn * 32 + p * 16 + brow) * LDSW + bcol;
                uint32 t[4];
                ldsm4(t, sm + 4 * BUF + off);
                bhi[2 * p][0] = t[0]; bhi[2 * p][1] = t[1];
                bhi[2 * p + 1][0] = t[2]; bhi[2 * p + 1][1] = t[3];
                ldsm4(t, sm + 6 * BUF + off);
                blo[2 * p][0] = t[0]; blo[2 * p][1] = t[1];
                blo[2 * p + 1][0] = t[2]; blo[2 * p + 1][1] = t[3];
            }
#pragma unroll
            for (int i = 0; i < 4; i++)
#pragma unroll
                for (int j = 0; j < 4; j++) {
                    mma16816(acc[i][j], ahi[i], bhi[j]);
                    mma16816(acc[i][j], ahi[i], blo[j]);
                    mma16816(acc[i][j], alo[i], bhi[j]);
                }
        }
        if (c + 1 < 32) SSTORE(1 - buf);
        __syncthreads();
    }

    // Epilogue: c0:(g,2tig) c1:(g,2tig+1) c2:(g+8,2tig) c3:(g+8,2tig+1)
    const int g_ = lane >> 2, tig = lane & 3;
#pragma unroll
    for (int i = 0; i < 4; i++)
#pragma unroll
        for (int j = 0; j < 4; j++)
#pragma unroll
            for (int r = 0; r < 4; r++) {
                int m = mBase + wm * 64 + i * 16 + g_ + ((r >> 1) << 3);
                int e = nBase + wn * 32 + j * 8 + tig * 2 + (r & 1);
                float val = acc[i][j][r] + bias[e];
                int b = m >> 10, t = m & 1023;
                int gg = e >> 10, nh = (e >> 7) & 7, d = e & 127;
                out[(((size_t)t * cB + b) * cNH + nh) * cQ + (size_t)gg * cD + d] = val;
            }
}

// ---------------------------------------------------------------------------
// Tiled fp32 GEMM with K-pair f32x2 accumulation (kept for phase 3).
//   C[r][e] = sum_k A[r][k] * Bm[e][k] + bias[e]
//   writes g_Wx layout (T,B,NH, (e&3)*128 + (e>>2))
// ---------------------------------------------------------------------------
template <int KK>
__global__ __launch_bounds__(256) void gemm_kernel(
    const float* __restrict__ A, const float* __restrict__ Bm,
    const float* __restrict__ bias, float* __restrict__ out)
{
    __shared__ float As[2][128][20];
    __shared__ float Bs[2][128][20];
    const int tid = threadIdx.x;
    const int tx = tid & 15, ty = tid >> 4;
    const int mBase = blockIdx.y * 128;
    const int nBase = blockIdx.x * 128;
    constexpr int NCH = KK / 16;

    float4 aR[2], bR[2];
    ull acc[8][8];
#pragma unroll
    for (int i = 0; i < 8; i++)
#pragma unroll
        for (int j = 0; j < 8; j++) acc[i][j] = 0ull;

#pragma unroll
    for (int s = 0; s < 2; s++) {
        int lin = s * 256 + tid;
        int row = lin >> 2, kv = lin & 3;
        aR[s] = *(const float4*)(A + (size_t)(mBase + row) * KK + kv * 4);
        bR[s] = *(const float4*)(Bm + (size_t)(nBase + row) * KK + kv * 4);
    }
#pragma unroll
    for (int s = 0; s < 2; s++) {
        int lin = s * 256 + tid;
        int row = lin >> 2, kv = lin & 3;
        *(float4*)&As[0][row][kv * 4] = aR[s];
        *(float4*)&Bs[0][row][kv * 4] = bR[s];
    }
    __syncthreads();

    for (int c = 0; c < NCH; c++) {
        const int buf = c & 1;
        if (c + 1 < NCH) {
            const int k0 = (c + 1) * 16;
#pragma unroll
            for (int s = 0; s < 2; s++) {
                int lin = s * 256 + tid;
                int row = lin >> 2, kv = lin & 3;
                aR[s] = *(const float4*)(A + (size_t)(mBase + row) * KK + k0 + kv * 4);
                bR[s] = *(const float4*)(Bm + (size_t)(nBase + row) * KK + k0 + kv * 4);
            }
        }
#pragma unroll
        for (int k4 = 0; k4 < 4; k4++) {
            longlong2 bv[8];
#pragma unroll
            for (int j = 0; j < 8; j++)
                bv[j] = *(const longlong2*)&Bs[buf][tx + 16 * j][k4 * 4];
#pragma unroll
            for (int i = 0; i < 8; i++) {
                longlong2 av = *(const longlong2*)&As[buf][ty + 16 * i][k4 * 4];
#pragma unroll
                for (int j = 0; j < 8; j++) {
                    acc[i][j] = ffma2((ull)av.x, (ull)bv[j].x, acc[i][j]);
                    acc[i][j] = ffma2((ull)av.y, (ull)bv[j].y, acc[i][j]);
                }
            }
        }
        if (c + 1 < NCH) {
            const int nb = 1 - buf;
#pragma unroll
            for (int s = 0; s < 2; s++) {
                int lin = s * 256 + tid;
                int row = lin >> 2, kv = lin & 3;
                *(float4*)&As[nb][row][kv * 4] = aR[s];
                *(float4*)&Bs[nb][row][kv * 4] = bR[s];
            }
        }
        __syncthreads();
    }

    float bs[8];
#pragma unroll
    for (int j = 0; j < 8; j++) bs[j] = bias[nBase + tx + 16 * j];
#pragma unroll
    for (int i = 0; i < 8; i++) {
        const int r = mBase + ty + 16 * i;
#pragma unroll
        for (int j = 0; j < 8; j++) {
            const int e = nBase + tx + 16 * j;
            float2 v = u2f2(acc[i][j]);
            float val = v.x + v.y + bs[j];
            out[(size_t)r * cQ + (size_t)(e & 3) * cD + (e >> 2)] = val;
        }
    }
}

// ---------------------------------------------------------------------------
// Persistent per-(head, batch-pair) LSTM scan (unchanged from R1/R3 passing).
// ---------------------------------------------------------------------------
__global__ __launch_bounds__(256) void lstm_scan_kernel(
    const float* __restrict__ Wx, const float* __restrict__ R,
    const float* __restrict__ Bg, float* __restrict__ hs_out,
    float* __restrict__ out, int layer)
{
    extern __shared__ char smem[];
    longlong2* R1s = (longlong2*)smem;              // 128 KB
    ull* hbuf = (ull*)(smem + 131072);              // 2 KB
    float* pre = (float*)(smem + 131072 + 2048);    // 4 KB

    const int tid = threadIdx.x;
    const int n = blockIdx.x >> 4;
    const int b0 = (blockIdx.x & 15) * 2;

    const float* Rh = R + (size_t)(layer * cNH + n) * cD * cG * cD;

    const int q0 = tid, d0 = q0 & 127, g0 = q0 >> 7;
    const ull* r0g = (const ull*)(Rh + ((size_t)d0 * 4 + g0) * cD);
    ull R0[64];
#pragma unroll
    for (int p = 0; p < 64; p++) R0[p] = r0g[p];

    const int q1 = 256 + tid, d1 = q1 & 127, g1 = q1 >> 7;
    const longlong2* r1g = (const longlong2*)(Rh + ((size_t)d1 * 4 + g1) * cD);
#pragma unroll
    for (int j4 = 0; j4 < 32; j4++) R1s[j4 * 256 + tid] = r1g[j4];

    const float bg0 = Bg[((size_t)(layer * cNH + n) * cD + d0) * 4 + g0];
    const float bg1 = Bg[((size_t)(layer * cNH + n) * cD + d1) * 4 + g1];

    hbuf[tid] = 0ull;
    float c = 0.0f;
    const int ub = tid >> 7, ud = tid & 127;

    const float* wxBase = Wx + ((size_t)b0 * cNH + n) * cQ;
    const size_t wxStep = (size_t)cB * cNH * cQ;
    const size_t HN_OFF = (size_t)cB * cT * cH;

    __syncthreads();

    for (int t = 0; t < cT; t++) {
        const float* wxp = wxBase + (size_t)t * wxStep;
        const float wx00 = wxp[q0];
        const float wx01 = wxp[cNH * cQ + q0];
        const float wx10 = wxp[q1];
        const float wx11 = wxp[cNH * cQ + q1];

        const int cur = t & 1;
        const longlong2* hA = (const longlong2*)(hbuf + (size_t)cur * 128);
        const longlong2* hB = (const longlong2*)(hbuf + (size_t)cur * 128 + 64);

        ull a00 = 0ull, a01 = 0ull, a10 = 0ull, a11 = 0ull;
#pragma unroll
        for (int j4 = 0; j4 < 32; j4++) {
            const longlong2 ha = hA[j4];
            const longlong2 hb = hB[j4];
            const longlong2 r1 = R1s[j4 * 256 + tid];
            a00 = ffma2(R0[2 * j4], (ull)ha.x, a00);
            a00 = ffma2(R0[2 * j4 + 1], (ull)ha.y, a00);
            a01 = ffma2(R0[2 * j4], (ull)hb.x, a01);
            a01 = ffma2(R0[2 * j4 + 1], (ull)hb.y, a01);
            a10 = ffma2((ull)r1.x, (ull)ha.x, a10);
            a10 = ffma2((ull)r1.y, (ull)ha.y, a10);
            a11 = ffma2((ull)r1.x, (ull)hb.x, a11);
            a11 = ffma2((ull)r1.y, (ull)hb.y, a11);
        }
        float2 v;
        v = u2f2(a00); pre[q0]       = v.x + v.y + wx00 + bg0;
        v = u2f2(a01); pre[512 + q0] = v.x + v.y + wx01 + bg0;
        v = u2f2(a10); pre[q1]       = v.x + v.y + wx10 + bg1;
        v = u2f2(a11); pre[512 + q1] = v.x + v.y + wx11 + bg1;
        __syncthreads();

        const float pi = pre[ub * 512 + 0 * cD + ud];
        const float pf = pre[ub * 512 + 1 * cD + ud];
        const float pz = pre[ub * 512 + 2 * cD + ud];
        const float po = pre[ub * 512 + 3 * cD + ud];
        const float gi = sigf(pi), gf = sigf(pf), gz = tanhf_(pz), go = sigf(po);
        c = gf * c + gi * gz;
        const float hn = go * tanhf_(c);

        const int nxt = (t + 1) & 1;
        float* hw = (float*)(hbuf + (size_t)nxt * 128 + (size_t)ub * 64);
        hw[ud] = hn;

        const int bg_ = b0 + ub;
        if (layer == 0)
            hs_out[(((size_t)t * cB + bg_) * cNH + n) * cD + ud] = hn;
        else
            out[((size_t)bg_ * cT + t) * cH + (size_t)n * cD + ud] = hn;

        if (t == cT - 1) {
            out[HN_OFF + (size_t)layer * cB * cH + (size_t)bg_ * cH + (size_t)n * cD + ud] = hn;
            out[HN_OFF + (size_t)2 * cB * cH + (size_t)layer * cB * cH + (size_t)bg_ * cH + (size_t)n * cD + ud] = c;
        }
        __syncthreads();
    }
}

// ---------------------------------------------------------------------------
extern "C" void kernel_launch(void* const* d_in, const int* in_sizes, int n_in,
                              void* d_out, int out_size) {
    const float* x   = (const float*)d_in[0];  // (B,T,IN)
    const float* W   = (const float*)d_in[1];  // (4H, IN)
    const float* Wb  = (const float*)d_in[2];  // (4H)
    const float* W2  = (const float*)d_in[3];  // (4D, D)
    const float* W2b = (const float*)d_in[4];  // (4D)
    const float* R   = (const float*)d_in[5];  // (L,NH,D,G,D)
    const float* Bg  = (const float*)d_in[6];  // (L,NH,D,G)
    float* out = (float*)d_out;

    float* Wx;  cudaGetSymbolAddress((void**)&Wx, g_Wx);
    float* hs0; cudaGetSymbolAddress((void**)&hs0, g_hs0);
    __nv_bfloat16 *xhi, *xlo, *Whi, *Wlo;
    cudaGetSymbolAddress((void**)&xhi, g_xhi);
    cudaGetSymbolAddress((void**)&xlo, g_xlo);
    cudaGetSymbolAddress((void**)&Whi, g_Whi);
    cudaGetSymbolAddress((void**)&Wlo, g_Wlo);

    const int SMEM_SCAN = 131072 + 2048 + 4096;
    cudaFuncSetAttribute(lstm_scan_kernel,
                         cudaFuncAttributeMaxDynamicSharedMemorySize, SMEM_SCAN);
    const int SMEM_MMA = 8 * 128 * 40 * 2;  // 81920 B
    cudaFuncSetAttribute(gemm_mma0,
                         cudaFuncAttributeMaxDynamicSharedMemorySize, SMEM_MMA);

    // Phase 0: bf16 hi/lo splits
    split_kernel<<<(int)((size_t)cB * cT * cIN / 1024), 256>>>(x, xhi, xlo);
    split_kernel<<<(int)((size_t)cG * cH * cIN / 1024), 256>>>(W, Whi, Wlo);
    // Phase 1: input projection on tensor cores (bf16x3)
    gemm_mma0<<<dim3(32, 256), 256, SMEM_MMA>>>(xhi, xlo, Whi, Wlo, Wb, Wx);
    // Phase 2: layer-0 scan
    lstm_scan_kernel<<<128, 256, SMEM_SCAN>>>(Wx, R, Bg, hs0, out, 0);
    // Phase 3: inter-layer projection (fp32 SIMT)
    gemm_kernel<cD><<<dim3(4, 2048), 256>>>(hs0, W2, W2b, Wx);
    // Phase 4: layer-1 scan (writes h, hn, cn)
    lstm_scan_kernel<<<128, 256, SMEM_SCAN>>>(Wx, R, Bg, hs0, out, 1);
}

// round 5
// speedup vs baseline: 1.8124x; 1.0985x over previous
#include <cuda_runtime.h>
#include <cuda_bf16.h>

typedef unsigned long long ull;
typedef unsigned int uint32;

#define cB 32
#define cT 1024
#define cIN 1024
#define cNH 8
#define cD 128
#define cG 4
#define cH 1024
#define cQ 512   // D*G

// Scratch (static __device__ arrays: allocation-free per harness rules)
__device__ float g_Wx[(size_t)cT * cB * cNH * cQ];   // gate preactivations, layout (T,B,NH,G,D)
__device__ __nv_bfloat16 g_xhi[(size_t)cB * cT * cIN];
__device__ __nv_bfloat16 g_xlo[(size_t)cB * cT * cIN];
__device__ __nv_bfloat16 g_Whi[(size_t)cG * cH * cIN];
__device__ __nv_bfloat16 g_Wlo[(size_t)cG * cH * cIN];
__device__ __nv_bfloat16 g_W2hi[(size_t)cG * cD * cD];
__device__ __nv_bfloat16 g_W2lo[(size_t)cG * cD * cD];
__device__ __nv_bfloat16 g_h0hi[(size_t)cT * cB * cNH * cD];  // layer-0 h, bf16 hi
__device__ __nv_bfloat16 g_h0lo[(size_t)cT * cB * cNH * cD];  // layer-0 h, bf16 lo

// ---------------------------------------------------------------------------
__device__ __forceinline__ ull ffma2(ull a, ull b, ull c) {
    ull d;
    asm("fma.rn.f32x2 %0, %1, %2, %3;" : "=l"(d) : "l"(a), "l"(b), "l"(c));
    return d;
}
__device__ __forceinline__ float2 u2f2(ull u) {
    float2 f;
    asm("mov.b64 {%0, %1}, %2;" : "=f"(f.x), "=f"(f.y) : "l"(u));
    return f;
}
__device__ __forceinline__ float sigf(float x) { return 1.0f / (1.0f + __expf(-x)); }
__device__ __forceinline__ float tanhf_(float x) { return 1.0f - 2.0f / (__expf(2.0f * x) + 1.0f); }

// ---------------------------------------------------------------------------
// fp32 -> bf16 hi/lo split
// ---------------------------------------------------------------------------
__global__ __launch_bounds__(256) void split_kernel(
    const float* __restrict__ in, __nv_bfloat16* __restrict__ hi,
    __nv_bfloat16* __restrict__ lo)
{
    size_t i = ((size_t)blockIdx.x * 256 + threadIdx.x) * 4;
    float4 v = *(const float4*)(in + i);
    __nv_bfloat16 h[4], l[4];
    float vv[4] = {v.x, v.y, v.z, v.w};
#pragma unroll
    for (int k = 0; k < 4; k++) {
        h[k] = __float2bfloat16_rn(vv[k]);
        l[k] = __float2bfloat16_rn(vv[k] - __bfloat162float(h[k]));
    }
    *(uint2*)(hi + i) = *(uint2*)h;
    *(uint2*)(lo + i) = *(uint2*)l;
}

// ---------------------------------------------------------------------------
// mma helpers
// ---------------------------------------------------------------------------
__device__ __forceinline__ void ldsm4(uint32* r, const __nv_bfloat16* p) {
    uint32 a = (uint32)__cvta_generic_to_shared(p);
    asm volatile("ldmatrix.sync.aligned.m8n8.x4.shared.b16 {%0,%1,%2,%3}, [%4];"
                 : "=r"(r[0]), "=r"(r[1]), "=r"(r[2]), "=r"(r[3]) : "r"(a));
}
__device__ __forceinline__ void mma16816(float* c, const uint32* a, const uint32* b) {
    asm volatile(
        "mma.sync.aligned.m16n8k16.row.col.f32.bf16.bf16.f32 "
        "{%0,%1,%2,%3}, {%4,%5,%6,%7}, {%8,%9}, {%0,%1,%2,%3};"
        : "+f"(c[0]), "+f"(c[1]), "+f"(c[2]), "+f"(c[3])
        : "r"(a[0]), "r"(a[1]), "r"(a[2]), "r"(a[3]), "r"(b[0]), "r"(b[1]));
}
__device__ __forceinline__ void cpasync16(const __nv_bfloat16* s, __nv_bfloat16* d) {
    uint32 a = (uint32)__cvta_generic_to_shared(d);
    asm volatile("cp.async.cg.shared.global [%0], [%1], 16;" :: "r"(a), "l"(s));
}
__device__ __forceinline__ void cp_commit() { asm volatile("cp.async.commit_group;"); }
__device__ __forceinline__ void cp_wait0() { asm volatile("cp.async.wait_group 0;"); }

// ---------------------------------------------------------------------------
// Phase-1 GEMM, bf16x3, CTA tile 128(M) x 256(N), BK=32, cp.async double-buffer.
// 8 warps as 2(M) x 4(N) -> warp tile 64x64.
// Grid: x = N-tile (16, fastest -> A block L2 reuse), y = M-tile (256).
// Epilogue scatters to g_Wx layout (T,B,NH,G,D).
// ---------------------------------------------------------------------------
__global__ __launch_bounds__(256) void gemm_mma0(
    const __nv_bfloat16* __restrict__ Ahi, const __nv_bfloat16* __restrict__ Alo,
    const __nv_bfloat16* __restrict__ Bhi, const __nv_bfloat16* __restrict__ Blo,
    const float* __restrict__ bias, float* __restrict__ out)
{
    extern __shared__ __nv_bfloat16 sm[];
    constexpr int LDSW = 40;            // padded row stride (bf16): conflict-free ldsm, 16B-aligned rows
    constexpr int BUFA = 128 * LDSW;    // 5120
    constexpr int BUFB = 256 * LDSW;    // 10240
    constexpr int BUFT = 2 * BUFA + 2 * BUFB;  // bf16 per buffer = 30720
    // layout per buffer: Ahi @0, Alo @BUFA, Bhi @2*BUFA, Blo @2*BUFA+BUFB

    const int tid = threadIdx.x;
    const int lane = tid & 31, w = tid >> 5;
    const int wm = w & 1, wn = w >> 1;
    const int mBase = blockIdx.y * 128;
    const int nBase = blockIdx.x * 256;

    float acc[4][8][4];
#pragma unroll
    for (int i = 0; i < 4; i++)
#pragma unroll
        for (int j = 0; j < 8; j++)
#pragma unroll
            for (int r = 0; r < 4; r++) acc[i][j][r] = 0.0f;

#define ISSUE(cc, bf)                                                           \
    {                                                                           \
        const int k0 = (cc) * 32;                                               \
        __nv_bfloat16* base = sm + (bf) * BUFT;                                 \
        _Pragma("unroll")                                                       \
        for (int s = 0; s < 2; s++) {  /* A: 128 rows x 4 uint4 */              \
            int lin = s * 256 + tid;                                            \
            int row = lin >> 2, kv = lin & 3;                                   \
            size_t ga = (size_t)(mBase + row) * cIN + k0 + kv * 8;              \
            int so = row * LDSW + kv * 8;                                       \
            cpasync16(Ahi + ga, base + so);                                     \
            cpasync16(Alo + ga, base + BUFA + so);                              \
        }                                                                       \
        _Pragma("unroll")                                                       \
        for (int s = 0; s < 4; s++) {  /* B: 256 rows x 4 uint4 */              \
            int lin = s * 256 + tid;                                            \
            int row = lin >> 2, kv = lin & 3;                                   \
            size_t gb = (size_t)(nBase + row) * cIN + k0 + kv * 8;              \
            int so = row * LDSW + kv * 8;                                       \
            cpasync16(Bhi + gb, base + 2 * BUFA + so);                          \
            cpasync16(Blo + gb, base + 2 * BUFA + BUFB + so);                   \
        }                                                                       \
        cp_commit();                                                            \
    }

    ISSUE(0, 0);

    const int arow = lane & 15;
    const int acolS = (lane >> 4) * 8;
    const int brow = (lane & 7) + ((lane >> 4) << 3);
    const int bcolS = ((lane >> 3) & 1) * 8;

    for (int c = 0; c < 32; c++) {
        const int buf = c & 1;
        cp_wait0();
        __syncthreads();
        if (c + 1 < 32) ISSUE(c + 1, 1 - buf);
        const __nv_bfloat16* base = sm + buf * BUFT;
#pragma unroll
        for (int st = 0; st < 2; st++) {
            const int kb = st * 16;
            uint32 ahi[4][4], alo[4][4];
#pragma unroll
            for (int i = 0; i < 4; i++) {
                int off = (wm * 64 + i * 16 + arow) * LDSW + kb + acolS;
                ldsm4(ahi[i], base + off);
                ldsm4(alo[i], base + BUFA + off);
            }
#pragma unroll
            for (int p = 0; p < 4; p++) {
                int off = (wn * 64 + p * 16 + brow) * LDSW + kb + bcolS;
                uint32 th[4], tl[4];
                ldsm4(th, base + 2 * BUFA + off);
                ldsm4(tl, base + 2 * BUFA + BUFB + off);
                uint32 bh0[2] = {th[0], th[1]}, bh1[2] = {th[2], th[3]};
                uint32 bl0[2] = {tl[0], tl[1]}, bl1[2] = {tl[2], tl[3]};
#pragma unroll
                for (int i = 0; i < 4; i++) {
                    mma16816(acc[i][2 * p], ahi[i], bh0);
                    mma16816(acc[i][2 * p], ahi[i], bl0);
                    mma16816(acc[i][2 * p], alo[i], bh0);
                    mma16816(acc[i][2 * p + 1], ahi[i], bh1);
                    mma16816(acc[i][2 * p + 1], ahi[i], bl1);
                    mma16816(acc[i][2 * p + 1], alo[i], bh1);
                }
            }
        }
        __syncthreads();
    }

    // Epilogue: scatter with bias. c-frag r: row += ((r>>1)<<3), col += (r&1)
    const int g_ = lane >> 2, tig = lane & 3;
#pragma unroll
    for (int i = 0; i < 4; i++)
#pragma unroll
        for (int j = 0; j < 8; j++)
#pragma unroll
            for (int r = 0; r < 4; r++) {
                int m = mBase + wm * 64 + i * 16 + g_ + ((r >> 1) << 3);
                int e = nBase + wn * 64 + j * 8 + tig * 2 + (r & 1);
                float val = acc[i][j][r] + bias[e];
                int b = m >> 10, t = m & 1023;
                int gg = e >> 10, nh = (e >> 7) & 7, d = e & 127;
                out[(((size_t)t * cB + b) * cNH + nh) * cQ + (size_t)gg * cD + d] = val;
            }
}

// ---------------------------------------------------------------------------
// Phase-3 GEMM, bf16x3, K=128 single-shot. CTA 128x128, warp tile 64x32.
// A rows = (t,b,n) of layer-0 h (bf16 hi/lo from scan); B = W2 rows (e,k).
// Writes g_Wx layout: out[r*cQ + (e&3)*cD + (e>>2)].
// ---------------------------------------------------------------------------
__global__ __launch_bounds__(256) void gemm_mma3(
    const __nv_bfloat16* __restrict__ Ahi, const __nv_bfloat16* __restrict__ Alo,
    const __nv_bfloat16* __restrict__ Bhi, const __nv_bfloat16* __restrict__ Blo,
    const float* __restrict__ bias, float* __restrict__ out)
{
    extern __shared__ __nv_bfloat16 sm3[];
    constexpr int LDSW = 136;          // 128 + 8 pad (272B rows, 16B-aligned)
    constexpr int BUF = 128 * LDSW;
    // Ahi @0, Alo @BUF, Bhi @2BUF, Blo @3BUF

    const int tid = threadIdx.x;
    const int lane = tid & 31, w = tid >> 5;
    const int wm = w & 1, wn = w >> 1;
    const int mBase = blockIdx.y * 128;
    const int nBase = blockIdx.x * 128;

    // load tiles: 128 rows x 16 uint4 each array
#pragma unroll
    for (int s = 0; s < 8; s++) {
        int lin = s * 256 + tid;
        int row = lin >> 4, kv = lin & 15;
        size_t ga = (size_t)(mBase + row) * cD + kv * 8;
        size_t gb = (size_t)(nBase + row) * cD + kv * 8;
        int so = row * LDSW + kv * 8;
        *(uint4*)(sm3 + so) = *(const uint4*)(Ahi + ga);
        *(uint4*)(sm3 + BUF + so) = *(const uint4*)(Alo + ga);
        *(uint4*)(sm3 + 2 * BUF + so) = *(const uint4*)(Bhi + gb);
        *(uint4*)(sm3 + 3 * BUF + so) = *(const uint4*)(Blo + gb);
    }
    __syncthreads();

    float acc[4][4][4];
#pragma unroll
    for (int i = 0; i < 4; i++)
#pragma unroll
        for (int j = 0; j < 4; j++)
#pragma unroll
            for (int r = 0; r < 4; r++) acc[i][j][r] = 0.0f;

    const int arow = lane & 15;
    const int acolS = (lane >> 4) * 8;
    const int brow = (lane & 7) + ((lane >> 4) << 3);
    const int bcolS = ((lane >> 3) & 1) * 8;

#pragma unroll
    for (int st = 0; st < 8; st++) {
        const int kb = st * 16;
        uint32 ahi[4][4], alo[4][4];
#pragma unroll
        for (int i = 0; i < 4; i++) {
            int off = (wm * 64 + i * 16 + arow) * LDSW + kb + acolS;
            ldsm4(ahi[i], sm3 + off);
            ldsm4(alo[i], sm3 + BUF + off);
        }
#pragma unroll
        for (int p = 0; p < 2; p++) {
            int off = (wn * 32 + p * 16 + brow) * LDSW + kb + bcolS;
            uint32 th[4], tl[4];
            ldsm4(th, sm3 + 2 * BUF + off);
            ldsm4(tl, sm3 + 3 * BUF + off);
            uint32 bh0[2] = {th[0], th[1]}, bh1[2] = {th[2], th[3]};
            uint32 bl0[2] = {tl[0], tl[1]}, bl1[2] = {tl[2], tl[3]};
#pragma unroll
            for (int i = 0; i < 4; i++) {
                mma16816(acc[i][2 * p], ahi[i], bh0);
                mma16816(acc[i][2 * p], ahi[i], bl0);
                mma16816(acc[i][2 * p], alo[i], bh0);
                mma16816(acc[i][2 * p + 1], ahi[i], bh1);
                mma16816(acc[i][2 * p + 1], ahi[i], bl1);
                mma16816(acc[i][2 * p + 1], alo[i], bh1);
            }
        }
    }

    const int g_ = lane >> 2, tig = lane & 3;
#pragma unroll
    for (int i = 0; i < 4; i++)
#pragma unroll
        for (int j = 0; j < 4; j++)
#pragma unroll
            for (int r = 0; r < 4; r++) {
                int m = mBase + wm * 64 + i * 16 + g_ + ((r >> 1) << 3);
                int e = nBase + wn * 32 + j * 8 + tig * 2 + (r & 1);
                float val = acc[i][j][r] + bias[e];
                out[(size_t)m * cQ + (size_t)(e & 3) * cD + (e >> 2)] = val;
            }
}

// ---------------------------------------------------------------------------
// Persistent per-(head, batch-pair) LSTM scan.
// Layer 0 additionally emits h as bf16 hi/lo for the phase-3 mma.
// ---------------------------------------------------------------------------
__global__ __launch_bounds__(256) void lstm_scan_kernel(
    const float* __restrict__ Wx, const float* __restrict__ R,
    const float* __restrict__ Bg, __nv_bfloat16* __restrict__ h0hi,
    __nv_bfloat16* __restrict__ h0lo, float* __restrict__ out, int layer)
{
    extern __shared__ char smem[];
    longlong2* R1s = (longlong2*)smem;              // 128 KB
    ull* hbuf = (ull*)(smem + 131072);              // 2 KB
    float* pre = (float*)(smem + 131072 + 2048);    // 4 KB

    const int tid = threadIdx.x;
    const int n = blockIdx.x >> 4;
    const int b0 = (blockIdx.x & 15) * 2;

    const float* Rh = R + (size_t)(layer * cNH + n) * cD * cG * cD;

    const int q0 = tid, d0 = q0 & 127, g0 = q0 >> 7;
    const ull* r0g = (const ull*)(Rh + ((size_t)d0 * 4 + g0) * cD);
    ull R0[64];
#pragma unroll
    for (int p = 0; p < 64; p++) R0[p] = r0g[p];

    const int q1 = 256 + tid, d1 = q1 & 127, g1 = q1 >> 7;
    const longlong2* r1g = (const longlong2*)(Rh + ((size_t)d1 * 4 + g1) * cD);
#pragma unroll
    for (int j4 = 0; j4 < 32; j4++) R1s[j4 * 256 + tid] = r1g[j4];

    const float bg0 = Bg[((size_t)(layer * cNH + n) * cD + d0) * 4 + g0];
    const float bg1 = Bg[((size_t)(layer * cNH + n) * cD + d1) * 4 + g1];

    hbuf[tid] = 0ull;
    float c = 0.0f;
    const int ub = tid >> 7, ud = tid & 127;

    const float* wxBase = Wx + ((size_t)b0 * cNH + n) * cQ;
    const size_t wxStep = (size_t)cB * cNH * cQ;
    const size_t HN_OFF = (size_t)cB * cT * cH;

    __syncthreads();

    for (int t = 0; t < cT; t++) {
        const float* wxp = wxBase + (size_t)t * wxStep;
        const float wx00 = wxp[q0];
        const float wx01 = wxp[cNH * cQ + q0];
        const float wx10 = wxp[q1];
        const float wx11 = wxp[cNH * cQ + q1];

        const int cur = t & 1;
        const longlong2* hA = (const longlong2*)(hbuf + (size_t)cur * 128);
        const longlong2* hB = (const longlong2*)(hbuf + (size_t)cur * 128 + 64);

        ull a00 = 0ull, a01 = 0ull, a10 = 0ull, a11 = 0ull;
#pragma unroll
        for (int j4 = 0; j4 < 32; j4++) {
            const longlong2 ha = hA[j4];
            const longlong2 hb = hB[j4];
            const longlong2 r1 = R1s[j4 * 256 + tid];
            a00 = ffma2(R0[2 * j4], (ull)ha.x, a00);
            a00 = ffma2(R0[2 * j4 + 1], (ull)ha.y, a00);
            a01 = ffma2(R0[2 * j4], (ull)hb.x, a01);
            a01 = ffma2(R0[2 * j4 + 1], (ull)hb.y, a01);
            a10 = ffma2((ull)r1.x, (ull)ha.x, a10);
            a10 = ffma2((ull)r1.y, (ull)ha.y, a10);
            a11 = ffma2((ull)r1.x, (ull)hb.x, a11);
            a11 = ffma2((ull)r1.y, (ull)hb.y, a11);
        }
        float2 v;
        v = u2f2(a00); pre[q0]       = v.x + v.y + wx00 + bg0;
        v = u2f2(a01); pre[512 + q0] = v.x + v.y + wx01 + bg0;
        v = u2f2(a10); pre[q1]       = v.x + v.y + wx10 + bg1;
        v = u2f2(a11); pre[512 + q1] = v.x + v.y + wx11 + bg1;
        __syncthreads();

        const float pi = pre[ub * 512 + 0 * cD + ud];
        const float pf = pre[ub * 512 + 1 * cD + ud];
        const float pz = pre[ub * 512 + 2 * cD + ud];
        const float po = pre[ub * 512 + 3 * cD + ud];
        const float gi = sigf(pi), gf = sigf(pf), gz = tanhf_(pz), go = sigf(po);
        c = gf * c + gi * gz;
        const float hn = go * tanhf_(c);

        const int nxt = (t + 1) & 1;
        float* hw = (float*)(hbuf + (size_t)nxt * 128 + (size_t)ub * 64);
        hw[ud] = hn;

        const int bg_ = b0 + ub;
        if (layer == 0) {
            const size_t idx = (((size_t)t * cB + bg_) * cNH + n) * cD + ud;
            __nv_bfloat16 hh = __float2bfloat16_rn(hn);
            h0hi[idx] = hh;
            h0lo[idx] = __float2bfloat16_rn(hn - __bfloat162float(hh));
        } else {
            out[((size_t)bg_ * cT + t) * cH + (size_t)n * cD + ud] = hn;
        }

        if (t == cT - 1) {
            out[HN_OFF + (size_t)layer * cB * cH + (size_t)bg_ * cH + (size_t)n * cD + ud] = hn;
            out[HN_OFF + (size_t)2 * cB * cH + (size_t)layer * cB * cH + (size_t)bg_ * cH + (size_t)n * cD + ud] = c;
        }
        __syncthreads();
    }
}

// ---------------------------------------------------------------------------
extern "C" void kernel_launch(void* const* d_in, const int* in_sizes, int n_in,
                              void* d_out, int out_size) {
    const float* x   = (const float*)d_in[0];  // (B,T,IN)
    const float* W   = (const float*)d_in[1];  // (4H, IN)
    const float* Wb  = (const float*)d_in[2];  // (4H)
    const float* W2  = (const float*)d_in[3];  // (4D, D)
    const float* W2b = (const float*)d_in[4];  // (4D)
    const float* R   = (const float*)d_in[5];  // (L,NH,D,G,D)
    const float* Bg  = (const float*)d_in[6];  // (L,NH,D,G)
    float* out = (float*)d_out;

    float* Wx;  cudaGetSymbolAddress((void**)&Wx, g_Wx);
    __nv_bfloat16 *xhi, *xlo, *Whi, *Wlo, *W2hi, *W2lo, *h0hi, *h0lo;
    cudaGetSymbolAddress((void**)&xhi, g_xhi);
    cudaGetSymbolAddress((void**)&xlo, g_xlo);
    cudaGetSymbolAddress((void**)&Whi, g_Whi);
    cudaGetSymbolAddress((void**)&Wlo, g_Wlo);
    cudaGetSymbolAddress((void**)&W2hi, g_W2hi);
    cudaGetSymbolAddress((void**)&W2lo, g_W2lo);
    cudaGetSymbolAddress((void**)&h0hi, g_h0hi);
    cudaGetSymbolAddress((void**)&h0lo, g_h0lo);

    const int SMEM_SCAN = 131072 + 2048 + 4096;
    cudaFuncSetAttribute(lstm_scan_kernel,
                         cudaFuncAttributeMaxDynamicSharedMemorySize, SMEM_SCAN);
    const int SMEM_MMA0 = 2 * (2 * 128 * 40 + 2 * 256 * 40) * 2;  // 122880 B
    cudaFuncSetAttribute(gemm_mma0,
                         cudaFuncAttributeMaxDynamicSharedMemorySize, SMEM_MMA0);
    const int SMEM_MMA3 = 4 * 128 * 136 * 2;  // 139264 B
    cudaFuncSetAttribute(gemm_mma3,
                         cudaFuncAttributeMaxDynamicSharedMemorySize, SMEM_MMA3);

    // Phase 0: bf16 hi/lo splits
    split_kernel<<<(int)((size_t)cB * cT * cIN / 1024), 256>>>(x, xhi, xlo);
    split_kernel<<<(int)((size_t)cG * cH * cIN / 1024), 256>>>(W, Whi, Wlo);
    split_kernel<<<(int)((size_t)cG * cD * cD / 1024), 256>>>(W2, W2hi, W2lo);
    // Phase 1: input projection on tensor cores (bf16x3), N-fastest raster
    gemm_mma0<<<dim3(16, 256), 256, SMEM_MMA0>>>(xhi, xlo, Whi, Wlo, Wb, Wx);
    // Phase 2: layer-0 scan (emits bf16 hi/lo h)
    lstm_scan_kernel<<<128, 256, SMEM_SCAN>>>(Wx, R, Bg, h0hi, h0lo, out, 0);
    // Phase 3: inter-layer projection on tensor cores (bf16x3)
    gemm_mma3<<<dim3(4, 2048), 256, SMEM_MMA3>>>(h0hi, h0lo, W2hi, W2lo, W2b, Wx);
    // Phase 4: layer-1 scan (writes h, hn, cn)
    lstm_scan_kernel<<<128, 256, SMEM_SCAN>>>(Wx, R, Bg, h0hi, h0lo, out, 1);
}

// round 8
// speedup vs baseline: 1.9055x; 1.0513x over previous
#include <cuda_runtime.h>
#include <cuda_bf16.h>

typedef unsigned long long ull;
typedef unsigned int uint32;

#define cB 32
#define cT 1024
#define cIN 1024
#define cNH 8
#define cD 128
#define cG 4
#define cH 1024
#define cQ 512   // D*G

// Scratch (static __device__ arrays: allocation-free per harness rules)
__device__ float g_Wx[(size_t)cT * cB * cNH * cQ];   // gate preactivations, layout (T,B,NH,G,D)
__device__ __nv_bfloat16 g_xhi[(size_t)cB * cT * cIN];
__device__ __nv_bfloat16 g_xlo[(size_t)cB * cT * cIN];
__device__ __nv_bfloat16 g_Whi[(size_t)cG * cH * cIN];
__device__ __nv_bfloat16 g_Wlo[(size_t)cG * cH * cIN];
__device__ __nv_bfloat16 g_W2hi[(size_t)cG * cD * cD];
__device__ __nv_bfloat16 g_W2lo[(size_t)cG * cD * cD];
__device__ __nv_bfloat16 g_h0hi[(size_t)cT * cB * cNH * cD];
__device__ __nv_bfloat16 g_h0lo[(size_t)cT * cB * cNH * cD];

// ---------------------------------------------------------------------------
__device__ __forceinline__ ull ffma2(ull a, ull b, ull c) {
    ull d;
    asm("fma.rn.f32x2 %0, %1, %2, %3;" : "=l"(d) : "l"(a), "l"(b), "l"(c));
    return d;
}
__device__ __forceinline__ float2 u2f2(ull u) {
    float2 f;
    asm("mov.b64 {%0, %1}, %2;" : "=f"(f.x), "=f"(f.y) : "l"(u));
    return f;
}
__device__ __forceinline__ float sigf(float x) { return 1.0f / (1.0f + __expf(-x)); }
__device__ __forceinline__ float tanhf_(float x) { return 1.0f - 2.0f / (__expf(2.0f * x) + 1.0f); }

// ---------------------------------------------------------------------------
// fp32 -> bf16 hi/lo split
// ---------------------------------------------------------------------------
__global__ __launch_bounds__(256) void split_kernel(
    const float* __restrict__ in, __nv_bfloat16* __restrict__ hi,
    __nv_bfloat16* __restrict__ lo)
{
    size_t i = ((size_t)blockIdx.x * 256 + threadIdx.x) * 4;
    float4 v = *(const float4*)(in + i);
    __nv_bfloat16 h[4], l[4];
    float vv[4] = {v.x, v.y, v.z, v.w};
#pragma unroll
    for (int k = 0; k < 4; k++) {
        h[k] = __float2bfloat16_rn(vv[k]);
        l[k] = __float2bfloat16_rn(vv[k] - __bfloat162float(h[k]));
    }
    *(uint2*)(hi + i) = *(uint2*)h;
    *(uint2*)(lo + i) = *(uint2*)l;
}

// ---------------------------------------------------------------------------
// warp-mma helpers
// ---------------------------------------------------------------------------
__device__ __forceinline__ void ldsm4(uint32* r, const __nv_bfloat16* p) {
    uint32 a = (uint32)__cvta_generic_to_shared(p);
    asm volatile("ldmatrix.sync.aligned.m8n8.x4.shared.b16 {%0,%1,%2,%3}, [%4];"
                 : "=r"(r[0]), "=r"(r[1]), "=r"(r[2]), "=r"(r[3]) : "r"(a));
}
__device__ __forceinline__ void mma16816(float* c, const uint32* a, const uint32* b) {
    asm volatile(
        "mma.sync.aligned.m16n8k16.row.col.f32.bf16.bf16.f32 "
        "{%0,%1,%2,%3}, {%4,%5,%6,%7}, {%8,%9}, {%0,%1,%2,%3};"
        : "+f"(c[0]), "+f"(c[1]), "+f"(c[2]), "+f"(c[3])
        : "r"(a[0]), "r"(a[1]), "r"(a[2]), "r"(a[3]), "r"(b[0]), "r"(b[1]));
}
__device__ __forceinline__ void cpasync16(const void* s, void* d) {
    uint32 a = (uint32)__cvta_generic_to_shared(d);
    asm volatile("cp.async.cg.shared.global [%0], [%1], 16;" :: "r"(a), "l"(s));
}
__device__ __forceinline__ void cp_commit() { asm volatile("cp.async.commit_group;"); }
__device__ __forceinline__ void cp_wait0() { asm volatile("cp.async.wait_group 0;"); }

// ---------------------------------------------------------------------------
// Phase-1 GEMM, bf16x3 warp-mma, CTA tile 128(M) x 256(N), BK=32, cp.async
// double-buffer. 8 warps as 2(M) x 4(N) -> warp tile 64x64.
// Grid: x = N-tile (16, fastest -> A block L2 reuse), y = M-tile (256).
// Epilogue scatters to g_Wx layout (T,B,NH,G,D).  [R5-passing version]
// ---------------------------------------------------------------------------
__global__ __launch_bounds__(256) void gemm_mma0(
    const __nv_bfloat16* __restrict__ Ahi, const __nv_bfloat16* __restrict__ Alo,
    const __nv_bfloat16* __restrict__ Bhi, const __nv_bfloat16* __restrict__ Blo,
    const float* __restrict__ bias, float* __restrict__ out)
{
    extern __shared__ __nv_bfloat16 sm[];
    constexpr int LDSW = 40;
    constexpr int BUFA = 128 * LDSW;
    constexpr int BUFB = 256 * LDSW;
    constexpr int BUFT = 2 * BUFA + 2 * BUFB;

    const int tid = threadIdx.x;
    const int lane = tid & 31, w = tid >> 5;
    const int wm = w & 1, wn = w >> 1;
    const int mBase = blockIdx.y * 128;
    const int nBase = blockIdx.x * 256;

    float acc[4][8][4];
#pragma unroll
    for (int i = 0; i < 4; i++)
#pragma unroll
        for (int j = 0; j < 8; j++)
#pragma unroll
            for (int r = 0; r < 4; r++) acc[i][j][r] = 0.0f;

#define ISSUE(cc, bf)                                                           \
    {                                                                           \
        const int k0 = (cc) * 32;                                               \
        __nv_bfloat16* base = sm + (bf) * BUFT;                                 \
        _Pragma("unroll")                                                       \
        for (int s = 0; s < 2; s++) {                                           \
            int lin = s * 256 + tid;                                            \
            int row = lin >> 2, kv = lin & 3;                                   \
            size_t ga = (size_t)(mBase + row) * cIN + k0 + kv * 8;              \
            int so = row * LDSW + kv * 8;                                       \
            cpasync16(Ahi + ga, base + so);                                     \
            cpasync16(Alo + ga, base + BUFA + so);                              \
        }                                                                       \
        _Pragma("unroll")                                                       \
        for (int s = 0; s < 4; s++) {                                           \
            int lin = s * 256 + tid;                                            \
            int row = lin >> 2, kv = lin & 3;                                   \
            size_t gb = (size_t)(nBase + row) * cIN + k0 + kv * 8;              \
            int so = row * LDSW + kv * 8;                                       \
            cpasync16(Bhi + gb, base + 2 * BUFA + so);                          \
            cpasync16(Blo + gb, base + 2 * BUFA + BUFB + so);                   \
        }                                                                       \
        cp_commit();                                                            \
    }

    ISSUE(0, 0);

    const int arow = lane & 15;
    const int acolS = (lane >> 4) * 8;
    const int brow = (lane & 7) + ((lane >> 4) << 3);
    const int bcolS = ((lane >> 3) & 1) * 8;

    for (int c = 0; c < 32; c++) {
        const int buf = c & 1;
        cp_wait0();
        __syncthreads();
        if (c + 1 < 32) ISSUE(c + 1, 1 - buf);
        const __nv_bfloat16* base = sm + buf * BUFT;
#pragma unroll
        for (int st = 0; st < 2; st++) {
            const int kb = st * 16;
            uint32 ahi[4][4], alo[4][4];
#pragma unroll
            for (int i = 0; i < 4; i++) {
                int off = (wm * 64 + i * 16 + arow) * LDSW + kb + acolS;
                ldsm4(ahi[i], base + off);
                ldsm4(alo[i], base + BUFA + off);
            }
#pragma unroll
            for (int p = 0; p < 4; p++) {
                int off = (wn * 64 + p * 16 + brow) * LDSW + kb + bcolS;
                uint32 th[4], tl[4];
                ldsm4(th, base + 2 * BUFA + off);
                ldsm4(tl, base + 2 * BUFA + BUFB + off);
                uint32 bh0[2] = {th[0], th[1]}, bh1[2] = {th[2], th[3]};
                uint32 bl0[2] = {tl[0], tl[1]}, bl1[2] = {tl[2], tl[3]};
#pragma unroll
                for (int i = 0; i < 4; i++) {
                    mma16816(acc[i][2 * p], ahi[i], bh0);
                    mma16816(acc[i][2 * p], ahi[i], bl0);
                    mma16816(acc[i][2 * p], alo[i], bh0);
                    mma16816(acc[i][2 * p + 1], ahi[i], bh1);
                    mma16816(acc[i][2 * p + 1], ahi[i], bl1);
                    mma16816(acc[i][2 * p + 1], alo[i], bh1);
                }
            }
        }
        __syncthreads();
    }

    const int g_ = lane >> 2, tig = lane & 3;
#pragma unroll
    for (int i = 0; i < 4; i++)
#pragma unroll
        for (int j = 0; j < 8; j++)
#pragma unroll
            for (int r = 0; r < 4; r++) {
                int m = mBase + wm * 64 + i * 16 + g_ + ((r >> 1) << 3);
                int e = nBase + wn * 64 + j * 8 + tig * 2 + (r & 1);
                float val = acc[i][j][r] + bias[e];
                int b = m >> 10, t = m & 1023;
                int gg = e >> 10, nh = (e >> 7) & 7, d = e & 127;
                out[(((size_t)t * cB + b) * cNH + nh) * cQ + (size_t)gg * cD + d] = val;
            }
}

// ---------------------------------------------------------------------------
// Phase-3 GEMM, bf16x3 warp-mma, K=128 single-shot. CTA 128x128, warp 64x32.
// ---------------------------------------------------------------------------
__global__ __launch_bounds__(256) void gemm_mma3(
    const __nv_bfloat16* __restrict__ Ahi, const __nv_bfloat16* __restrict__ Alo,
    const __nv_bfloat16* __restrict__ Bhi, const __nv_bfloat16* __restrict__ Blo,
    const float* __restrict__ bias, float* __restrict__ out)
{
    extern __shared__ __nv_bfloat16 sm3[];
    constexpr int LDSW = 136;
    constexpr int BUF = 128 * LDSW;

    const int tid = threadIdx.x;
    const int lane = tid & 31, w = tid >> 5;
    const int wm = w & 1, wn = w >> 1;
    const int mBase = blockIdx.y * 128;
    const int nBase = blockIdx.x * 128;

#pragma unroll
    for (int s = 0; s < 8; s++) {
        int lin = s * 256 + tid;
        int row = lin >> 4, kv = lin & 15;
        size_t ga = (size_t)(mBase + row) * cD + kv * 8;
        size_t gb = (size_t)(nBase + row) * cD + kv * 8;
        int so = row * LDSW + kv * 8;
        *(uint4*)(sm3 + so) = *(const uint4*)(Ahi + ga);
        *(uint4*)(sm3 + BUF + so) = *(const uint4*)(Alo + ga);
        *(uint4*)(sm3 + 2 * BUF + so) = *(const uint4*)(Bhi + gb);
        *(uint4*)(sm3 + 3 * BUF + so) = *(const uint4*)(Blo + gb);
    }
    __syncthreads();

    float acc[4][4][4];
#pragma unroll
    for (int i = 0; i < 4; i++)
#pragma unroll
        for (int j = 0; j < 4; j++)
#pragma unroll
            for (int r = 0; r < 4; r++) acc[i][j][r] = 0.0f;

    const int arow = lane & 15;
    const int acolS = (lane >> 4) * 8;
    const int brow = (lane & 7) + ((lane >> 4) << 3);
    const int bcolS = ((lane >> 3) & 1) * 8;

#pragma unroll
    for (int st = 0; st < 8; st++) {
        const int kb = st * 16;
        uint32 ahi[4][4], alo[4][4];
#pragma unroll
        for (int i = 0; i < 4; i++) {
            int off = (wm * 64 + i * 16 + arow) * LDSW + kb + acolS;
            ldsm4(ahi[i], sm3 + off);
            ldsm4(alo[i], sm3 + BUF + off);
        }
#pragma unroll
        for (int p = 0; p < 2; p++) {
            int off = (wn * 32 + p * 16 + brow) * LDSW + kb + bcolS;
            uint32 th[4], tl[4];
            ldsm4(th, sm3 + 2 * BUF + off);
            ldsm4(tl, sm3 + 3 * BUF + off);
            uint32 bh0[2] = {th[0], th[1]}, bh1[2] = {th[2], th[3]};
            uint32 bl0[2] = {tl[0], tl[1]}, bl1[2] = {tl[2], tl[3]};
#pragma unroll
            for (int i = 0; i < 4; i++) {
                mma16816(acc[i][2 * p], ahi[i], bh0);
                mma16816(acc[i][2 * p], ahi[i], bl0);
                mma16816(acc[i][2 * p], alo[i], bh0);
                mma16816(acc[i][2 * p + 1], ahi[i], bh1);
                mma16816(acc[i][2 * p + 1], ahi[i], bl1);
                mma16816(acc[i][2 * p + 1], alo[i], bh1);
            }
        }
    }

    const int g_ = lane >> 2, tig = lane & 3;
#pragma unroll
    for (int i = 0; i < 4; i++)
#pragma unroll
        for (int j = 0; j < 4; j++)
#pragma unroll
            for (int r = 0; r < 4; r++) {
                int m = mBase + wm * 64 + i * 16 + g_ + ((r >> 1) << 3);
                int e = nBase + wn * 32 + j * 8 + tig * 2 + (r & 1);
                float val = acc[i][j][r] + bias[e];
                out[(size_t)m * cQ + (size_t)(e & 3) * cD + (e >> 2)] = val;
            }
}

// ---------------------------------------------------------------------------
// LSTM scan v2: gate-paired rows + shuffle epilogue, 1 sync/step.
// Grid 128 CTAs (head n = blk>>4, batch-pair b0), 256 threads.
// Thread t: j = t>>1 (d index), s = t&1.
//   owns row q1 = s*128+j     (gate s   : i or f) -> FULL K in regs (64 ull)
//   owns row q2 = (2+s)*128+j (gate 2+s : z or o) -> k<32 regs, k>=32 smem
//   both batches (b0, b0+1) -> 4 accumulators.
// Gates for (batch, d): threads 2j / 2j+1 exchange 2 values via shfl.xor 1;
// thread with s computes batch b0+s update. h-state double-buffered in smem.
// ---------------------------------------------------------------------------
__global__ __launch_bounds__(256) void lstm_scan2(
    const float* __restrict__ Wx, const float* __restrict__ R,
    const float* __restrict__ Bg, __nv_bfloat16* __restrict__ h0hi,
    __nv_bfloat16* __restrict__ h0lo, float* __restrict__ out, int layer)
{
    extern __shared__ char smem[];
    float4* R2s = (float4*)smem;              // [24 jj][256 tid] 16B = 96 KB
    float* hbuf = (float*)(smem + 98304);     // [2 buf][2 b][128 k] = 2 KB

    const int tid = threadIdx.x;
    const int n  = blockIdx.x >> 4;
    const int b0 = (blockIdx.x & 15) * 2;
    const int j  = tid >> 1;                  // d index
    const int s  = tid & 1;                   // row-set selector

    const float* Rh = R + (size_t)(layer * cNH + n) * cD * cG * cD;
    const float* r1g = Rh + ((size_t)j * 4 + s) * cD;        // gate s
    const float* r2g = Rh + ((size_t)j * 4 + 2 + s) * cD;    // gate 2+s

    ull RA[64];
#pragma unroll
    for (int p = 0; p < 64; p++) RA[p] = ((const ull*)r1g)[p];
    ull RB[16];
#pragma unroll
    for (int p = 0; p < 16; p++) RB[p] = ((const ull*)r2g)[p];
#pragma unroll
    for (int jj = 0; jj < 24; jj++)
        R2s[jj * 256 + tid] = *(const float4*)(r2g + 32 + jj * 4);

    const float bg1 = Bg[((size_t)(layer * cNH + n) * cD + j) * 4 + s];
    const float bg2 = Bg[((size_t)(layer * cNH + n) * cD + j) * 4 + 2 + s];

    hbuf[tid] = 0.0f;          // zero both h buffers (512 floats)
    hbuf[256 + tid] = 0.0f;
    float c = 0.0f;

    const float* wxBase = Wx + ((size_t)b0 * cNH + n) * cQ;
    const size_t wxStep = (size_t)cB * cNH * cQ;
    const size_t HN_OFF = (size_t)cB * cT * cH;
    const int q1 = s * cD + j, q2 = (2 + s) * cD + j;
    const int bg_ = b0 + s;    // batch this thread updates

    __syncthreads();

    for (int t = 0; t < cT; t++) {
        const float* wxp = wxBase + (size_t)t * wxStep;
        const float wx1A = wxp[q1];
        const float wx1B = wxp[cNH * cQ + q1];
        const float wx2A = wxp[q2];
        const float wx2B = wxp[cNH * cQ + q2];

        const int cur = t & 1;
        const float4* hA4 = (const float4*)(hbuf + cur * 256);
        const float4* hB4 = (const float4*)(hbuf + cur * 256 + 128);

        ull a1A = 0, a1B = 0, a2A = 0, a2B = 0;
#pragma unroll
        for (int i = 0; i < 32; i++) {
            const float4 ha = hA4[i];
            const float4 hb = hB4[i];
            const ull haL = ((const ull*)&ha)[0], haH = ((const ull*)&ha)[1];
            const ull hbL = ((const ull*)&hb)[0], hbH = ((const ull*)&hb)[1];
            a1A = ffma2(RA[2 * i], haL, a1A);
            a1A = ffma2(RA[2 * i + 1], haH, a1A);
            a1B = ffma2(RA[2 * i], hbL, a1B);
            a1B = ffma2(RA[2 * i + 1], hbH, a1B);
            ull r2l, r2h;
            if (i < 8) {
                r2l = RB[2 * i]; r2h = RB[2 * i + 1];
            } else {
                const float4 r2 = R2s[(i - 8) * 256 + tid];
                r2l = ((const ull*)&r2)[0]; r2h = ((const ull*)&r2)[1];
            }
            a2A = ffma2(r2l, haL, a2A);
            a2A = ffma2(r2h, haH, a2A);
            a2B = ffma2(r2l, hbL, a2B);
            a2B = ffma2(r2h, hbH, a2B);
        }

        float2 v;
        v = u2f2(a1A); const float p1A = v.x + v.y + wx1A + bg1;
        v = u2f2(a1B); const float p1B = v.x + v.y + wx1B + bg1;
        v = u2f2(a2A); const float p2A = v.x + v.y + wx2A + bg2;
        v = u2f2(a2B); const float p2B = v.x + v.y + wx2B + bg2;

        // exchange the partner-batch values with lane^1
        const float send1 = s ? p1A : p1B;
        const float send2 = s ? p2A : p2B;
        const float recv1 = __shfl_xor_sync(0xFFFFFFFFu, send1, 1);
        const float recv2 = __shfl_xor_sync(0xFFFFFFFFu, send2, 1);

        const float pX1 = s ? p1B : p1A;   // own-batch, gate s
        const float pX2 = s ? p2B : p2A;   // own-batch, gate 2+s
        const float ip = s ? recv1 : pX1;  // i-gate pre
        const float fp = s ? pX1 : recv1;  // f-gate pre
        const float zp = s ? recv2 : pX2;  // z-gate pre
        const float op = s ? pX2 : recv2;  // o-gate pre

        const float gi = sigf(ip), gf = sigf(fp), gz = tanhf_(zp), go = sigf(op);
        c = gf * c + gi * gz;
        const float hn = go * tanhf_(c);

        const int nxt = (t + 1) & 1;
        hbuf[nxt * 256 + s * 128 + j] = hn;

        if (layer == 0) {
            const size_t idx = (((size_t)t * cB + bg_) * cNH + n) * cD + j;
            const __nv_bfloat16 hh = __float2bfloat16_rn(hn);
            h0hi[idx] = hh;
            h0lo[idx] = __float2bfloat16_rn(hn - __bfloat162float(hh));
        } else {
            out[((size_t)bg_ * cT + t) * cH + (size_t)n * cD + j] = hn;
        }
        if (t == cT - 1) {
            out[HN_OFF + (size_t)layer * cB * cH + (size_t)bg_ * cH + (size_t)n * cD + j] = hn;
            out[HN_OFF + (size_t)2 * cB * cH + (size_t)layer * cB * cH + (size_t)bg_ * cH + (size_t)n * cD + j] = c;
        }
        __syncthreads();   // h(t+1) visible before next step's matvec
    }
}

// ---------------------------------------------------------------------------
extern "C" void kernel_launch(void* const* d_in, const int* in_sizes, int n_in,
                              void* d_out, int out_size) {
    const float* x   = (const float*)d_in[0];
    const float* W   = (const float*)d_in[1];
    const float* Wb  = (const float*)d_in[2];
    const float* W2  = (const float*)d_in[3];
    const float* W2b = (const float*)d_in[4];
    const float* R   = (const float*)d_in[5];
    const float* Bg  = (const float*)d_in[6];
    float* out = (float*)d_out;

    float* Wx;  cudaGetSymbolAddress((void**)&Wx, g_Wx);
    __nv_bfloat16 *xhi, *xlo, *Whi, *Wlo, *W2hi, *W2lo, *h0hi, *h0lo;
    cudaGetSymbolAddress((void**)&xhi, g_xhi);
    cudaGetSymbolAddress((void**)&xlo, g_xlo);
    cudaGetSymbolAddress((void**)&Whi, g_Whi);
    cudaGetSymbolAddress((void**)&Wlo, g_Wlo);
    cudaGetSymbolAddress((void**)&W2hi, g_W2hi);
    cudaGetSymbolAddress((void**)&W2lo, g_W2lo);
    cudaGetSymbolAddress((void**)&h0hi, g_h0hi);
    cudaGetSymbolAddress((void**)&h0lo, g_h0lo);

    const int SMEM_SCAN = 98304 + 2048;   // 100352
    cudaFuncSetAttribute(lstm_scan2,
                         cudaFuncAttributeMaxDynamicSharedMemorySize, SMEM_SCAN);
    const int SMEM_MMA0 = 2 * (2 * 128 * 40 + 2 * 256 * 40) * 2;  // 122880
    cudaFuncSetAttribute(gemm_mma0,
                         cudaFuncAttributeMaxDynamicSharedMemorySize, SMEM_MMA0);
    const int SMEM_MMA3 = 4 * 128 * 136 * 2;  // 139264
    cudaFuncSetAttribute(gemm_mma3,
                         cudaFuncAttributeMaxDynamicSharedMemorySize, SMEM_MMA3);

    // Phase 0: bf16 hi/lo splits
    split_kernel<<<(int)((size_t)cB * cT * cIN / 1024), 256>>>(x, xhi, xlo);
    split_kernel<<<(int)((size_t)cG * cH * cIN / 1024), 256>>>(W, Whi, Wlo);
    split_kernel<<<(int)((size_t)cG * cD * cD / 1024), 256>>>(W2, W2hi, W2lo);
    // Phase 1: input projection (warp-mma bf16x3, R5-passing)
    gemm_mma0<<<dim3(16, 256), 256, SMEM_MMA0>>>(xhi, xlo, Whi, Wlo, Wb, Wx);
    // Phase 2: layer-0 scan (v2)
    lstm_scan2<<<128, 256, SMEM_SCAN>>>(Wx, R, Bg, h0hi, h0lo, out, 0);
    // Phase 3: inter-layer projection (warp-mma bf16x3)
    gemm_mma3<<<dim3(4, 2048), 256, SMEM_MMA3>>>(h0hi, h0lo, W2hi, W2lo, W2b, Wx);
    // Phase 4: layer-1 scan (v2)
    lstm_scan2<<<128, 256, SMEM_SCAN>>>(Wx, R, Bg, h0hi, h0lo, out, 1);
}